// round 2
// baseline (speedup 1.0000x reference)
#include <cuda_runtime.h>
#include <cstdint>

// PatchPermAugmentation: x (B,T,N,C)=(32,1024,512,3) fp32, perm (B, NB=512) int32.
// out[b,t,n,0] = x[b, perm[b,t/2]*2 + t%2, n, 0]; out[b,t,n,1:] = x[b,t,n,1:].
//
// One CTA per patch block (b, blk): both rows t=2*blk and t=2*blk+1 use the
// same perm entry, and the block's 2*1536 = 3072 floats (768 float4) are
// contiguous in memory. Identity blocks (src_blk == blk, ~75-87%) reduce to a
// pure vectorized copy. Permuted blocks additionally read the contiguous src
// block and select components by (float4 index) % 3:
//   m==0 -> {x,w} from src; m==1 -> {z}; m==2 -> {y}.
// Output is never re-read -> streaming stores (__stcs) keep L2 for src reuse.

#define BB 32
#define TT 1024
#define NN 512
#define PSZ 2
#define NBLK (TT / PSZ)                 // 512
#define ROW_VEC4 ((NN * 3) / 4)         // 384
#define BLK_VEC4 (PSZ * ROW_VEC4)       // 768

__global__ __launch_bounds__(256)
void patch_perm_kernel(const float4* __restrict__ x,
                       const int* __restrict__ perm,
                       float4* __restrict__ out) {
    const int gblk = blockIdx.x;               // b*NBLK + blk, 0..16383
    const int blk = gblk & (NBLK - 1);
    const int src_blk = perm[gblk];            // perm is (B, NBLK) contiguous

    const size_t base = (size_t)gblk * BLK_VEC4;
    const float4* __restrict__ idr = x + base;
    float4* __restrict__ outr = out + base;

    const int i0 = threadIdx.x;                // 0..255
    const int i1 = i0 + 256;
    const int i2 = i0 + 512;

    // Front-batched identity loads (MLP >= 3)
    float4 v0 = idr[i0];
    float4 v1 = idr[i1];
    float4 v2 = idr[i2];

    if (src_blk != blk) {                      // uniform branch per CTA
        const float4* __restrict__ sr =
            x + ((size_t)(gblk - blk) + src_blk) * BLK_VEC4;
        float4 s0 = sr[i0];
        float4 s1 = sr[i1];
        float4 s2 = sr[i2];

        int m0 = i0 % 3;
        if (m0 == 0)      { v0.x = s0.x; v0.w = s0.w; }
        else if (m0 == 1) { v0.z = s0.z; }
        else              { v0.y = s0.y; }

        int m1 = i1 % 3;
        if (m1 == 0)      { v1.x = s1.x; v1.w = s1.w; }
        else if (m1 == 1) { v1.z = s1.z; }
        else              { v1.y = s1.y; }

        int m2 = i2 % 3;
        if (m2 == 0)      { v2.x = s2.x; v2.w = s2.w; }
        else if (m2 == 1) { v2.z = s2.z; }
        else              { v2.y = s2.y; }
    }

    __stcs(outr + i0, v0);
    __stcs(outr + i1, v1);
    __stcs(outr + i2, v2);
}

extern "C" void kernel_launch(void* const* d_in, const int* in_sizes, int n_in,
                              void* d_out, int out_size) {
    const float4* x = (const float4*)d_in[0];
    const int* perm = (const int*)d_in[1];
    float4* out = (float4*)d_out;

    dim3 grid(BB * NBLK);   // 16384 patch blocks
    dim3 block(256);
    patch_perm_kernel<<<grid, block>>>(x, perm, out);
}